// round 7
// baseline (speedup 1.0000x reference)
#include <cuda_runtime.h>

#define NSLICE 24
#define H 256
#define W 256
#define OH 512
#define OW 512

// One block = 8 output rows of one (b,s) image: rows 8g..8g+7, from 6 input
// rows iy = 4g-1 .. 4g+4. 128 threads; thread t produces output cols
// [4t, 4t+3] of all 8 rows via streaming float4 stores.
// Software-pipelined over input rows: only 3 input rows live at a time
// (12 data floats) to keep registers low WITHOUT a spill-forcing cap.
__device__ __forceinline__ void load_row(
    const float* __restrict__ xb, int iy, int t, int lane,
    float& L, float& cx, float& cy, float& R)
{
    const unsigned full = 0xFFFFFFFFu;
    const bool in = (iy >= 0) && (iy < H);
    float2 v = make_float2(0.f, 0.f);
    if (in) v = *reinterpret_cast<const float2*>(xb + iy * W + 2 * t);
    cx = v.x;
    cy = v.y;
    L = __shfl_up_sync(full, cy, 1);
    R = __shfl_down_sync(full, cx, 1);
    if (lane == 0)  L = (t > 0 && in)          ? xb[iy * W + 2 * t - 1] : 0.f;
    if (lane == 31) R = (2 * t + 2 < W && in)  ? xb[iy * W + 2 * t + 2] : 0.f;
}

__global__ __launch_bounds__(128, 10) void convT_kernel(
    const float* __restrict__ x,
    const float* __restrict__ w,
    const float* __restrict__ bias,
    float* __restrict__ out)
{
    const int t    = threadIdx.x;      // 0..127
    const int lane = t & 31;
    const int g    = blockIdx.x;       // 0..63 -> output rows 8g..8g+7
    const int bs   = blockIdx.y;       // 0..B*NSLICE-1
    const int s    = bs % NSLICE;

    // Uniform (warp-broadcast) weight loads.
    const float4 wr0 = *reinterpret_cast<const float4*>(w + s * 16 + 0);
    const float4 wr1 = *reinterpret_cast<const float4*>(w + s * 16 + 4);
    const float4 wr2 = *reinterpret_cast<const float4*>(w + s * 16 + 8);
    const float4 wr3 = *reinterpret_cast<const float4*>(w + s * 16 + 12);
    const float b0 = bias[s];

    const float w00 = wr0.x, w01 = wr0.y, w02 = wr0.z, w03 = wr0.w;
    const float w10 = wr1.x, w11 = wr1.y, w12 = wr1.z, w13 = wr1.w;
    const float w20 = wr2.x, w21 = wr2.y, w22 = wr2.z, w23 = wr2.w;
    const float w30 = wr3.x, w31 = wr3.y, w32 = wr3.z, w33 = wr3.w;

    const float* xb = x + (size_t)bs * (H * W);
    float* ob = out + (size_t)bs * (OH * OW) + (size_t)8 * g * OW + 4 * t;

    // Even output row 2r: input rows (r-1 -> w3*), (r -> w1*)
    // Odd  output row 2r+1: input rows (r -> w2*), (r+1 -> w0*)
#define OUT_ROW(rowidx, aL, acx, acy, aR, a0_, a1_, a2_, a3_,                  \
                        bL, bcx, bcy, bR, c0_, c1_, c2_, c3_)                  \
    {                                                                          \
        float4 o;                                                              \
        o.x = a3_ * aL  + a1_ * acx + c3_ * bL  + c1_ * bcx + b0;              \
        o.y = a2_ * acx + a0_ * acy + c2_ * bcx + c0_ * bcy + b0;              \
        o.z = a3_ * acx + a1_ * acy + c3_ * bcx + c1_ * bcy + b0;              \
        o.w = a2_ * acy + a0_ * aR  + c2_ * bcy + c0_ * bR  + b0;              \
        __stcs(reinterpret_cast<float4*>(ob + (size_t)(rowidx) * OW), o);      \
    }

    // Rolling row registers: A, B, C (A oldest).
    float AL, Acx, Acy, AR;
    float BL, Bcx, Bcy, BR;
    float CL, Ccx, Ccy, CR;

    const int iy0 = 4 * g - 1;
    load_row(xb, iy0 + 0, t, lane, AL, Acx, Acy, AR);   // row j=0
    load_row(xb, iy0 + 1, t, lane, BL, Bcx, Bcy, BR);   // row j=1

    // out0: rows (0:w3*, 1:w1*)
    OUT_ROW(0, AL, Acx, Acy, AR, w30, w31, w32, w33,
               BL, Bcx, Bcy, BR, w10, w11, w12, w13);

    load_row(xb, iy0 + 2, t, lane, CL, Ccx, Ccy, CR);   // row j=2
    // out1: rows (1:w2*, 2:w0*); out2: rows (1:w3*, 2:w1*)
    OUT_ROW(1, BL, Bcx, Bcy, BR, w20, w21, w22, w23,
               CL, Ccx, Ccy, CR, w00, w01, w02, w03);
    OUT_ROW(2, BL, Bcx, Bcy, BR, w30, w31, w32, w33,
               CL, Ccx, Ccy, CR, w10, w11, w12, w13);

    load_row(xb, iy0 + 3, t, lane, AL, Acx, Acy, AR);   // row j=3 (reuse A)
    // out3: rows (2:w2*, 3:w0*); out4: rows (2:w3*, 3:w1*)
    OUT_ROW(3, CL, Ccx, Ccy, CR, w20, w21, w22, w23,
               AL, Acx, Acy, AR, w00, w01, w02, w03);
    OUT_ROW(4, CL, Ccx, Ccy, CR, w30, w31, w32, w33,
               AL, Acx, Acy, AR, w10, w11, w12, w13);

    load_row(xb, iy0 + 4, t, lane, BL, Bcx, Bcy, BR);   // row j=4 (reuse B)
    // out5: rows (3:w2*, 4:w0*); out6: rows (3:w3*, 4:w1*)
    OUT_ROW(5, AL, Acx, Acy, AR, w20, w21, w22, w23,
               BL, Bcx, Bcy, BR, w00, w01, w02, w03);
    OUT_ROW(6, AL, Acx, Acy, AR, w30, w31, w32, w33,
               BL, Bcx, Bcy, BR, w10, w11, w12, w13);

    load_row(xb, iy0 + 5, t, lane, CL, Ccx, Ccy, CR);   // row j=5 (reuse C)
    // out7: rows (4:w2*, 5:w0*)
    OUT_ROW(7, BL, Bcx, Bcy, BR, w20, w21, w22, w23,
               CL, Ccx, Ccy, CR, w00, w01, w02, w03);
#undef OUT_ROW
}

extern "C" void kernel_launch(void* const* d_in, const int* in_sizes, int n_in,
                              void* d_out, int out_size) {
    const float* x = (const float*)d_in[0];
    const float* w = (const float*)d_in[1];
    const float* b = (const float*)d_in[2];
    float* out = (float*)d_out;

    const int B = in_sizes[0] / (NSLICE * H * W);   // = 8
    dim3 grid(OH / 8, B * NSLICE);                   // 64 x 192
    convT_kernel<<<grid, 128>>>(x, w, b, out);
}

// round 8
// speedup vs baseline: 1.1777x; 1.1777x over previous
#include <cuda_runtime.h>
#include <cstdint>

#define NSLICE 24
#define H 256
#define W 256
#define OH 512
#define OW 512

// One block = 8 output rows of one (b,s) image: rows 8g..8g+7, from 6 input
// rows iy = 4g-1 .. 4g+4 (all loaded up front, MLP=6). Thread t computes
// output cols [4t,4t+3] of all 8 rows into a 16KB smem tile; the tile (which
// is CONTIGUOUS in gmem: 8 full rows) is then pushed by one
// cp.async.bulk shared->global per block (bulk async engine, no STG path).
__global__ __launch_bounds__(128, 10) void convT_kernel(
    const float* __restrict__ x,
    const float* __restrict__ w,
    const float* __restrict__ bias,
    float* __restrict__ out)
{
    __shared__ alignas(128) float sbuf[8 * OW];   // 16 KB

    const int t  = threadIdx.x;        // 0..127
    const int g  = blockIdx.x;         // 0..63 -> output rows 8g..8g+7
    const int bs = blockIdx.y;         // 0..B*NSLICE-1
    const int s  = bs % NSLICE;

    // Uniform (warp-broadcast) weight loads.
    const float4 wr0 = *reinterpret_cast<const float4*>(w + s * 16 + 0);
    const float4 wr1 = *reinterpret_cast<const float4*>(w + s * 16 + 4);
    const float4 wr2 = *reinterpret_cast<const float4*>(w + s * 16 + 8);
    const float4 wr3 = *reinterpret_cast<const float4*>(w + s * 16 + 12);
    const float b0 = bias[s];

    const float* xb = x + (size_t)bs * (H * W);

    // 6 input rows j=0..5: iy = 4g - 1 + j. All loads batched up front.
    float cx[6], cy[6], L[6], R[6];
    #pragma unroll
    for (int j = 0; j < 6; ++j) {
        const int iy = 4 * g - 1 + j;
        float2 v = make_float2(0.f, 0.f);
        if (iy >= 0 && iy < H)
            v = *reinterpret_cast<const float2*>(xb + iy * W + 2 * t);
        cx[j] = v.x;
        cy[j] = v.y;
    }

    const unsigned full = 0xFFFFFFFFu;
    #pragma unroll
    for (int j = 0; j < 6; ++j) {
        L[j] = __shfl_up_sync(full, cy[j], 1);
        R[j] = __shfl_down_sync(full, cx[j], 1);
    }

    const int lane = t & 31;
    if (lane == 0) {
        #pragma unroll
        for (int j = 0; j < 6; ++j) {
            const int iy = 4 * g - 1 + j;
            L[j] = (t > 0 && iy >= 0 && iy < H) ? xb[iy * W + 2 * t - 1] : 0.f;
        }
    }
    if (lane == 31) {
        #pragma unroll
        for (int j = 0; j < 6; ++j) {
            const int iy = 4 * g - 1 + j;
            R[j] = (2 * t + 2 < W && iy >= 0 && iy < H) ? xb[iy * W + 2 * t + 2] : 0.f;
        }
    }

    const float w00 = wr0.x, w01 = wr0.y, w02 = wr0.z, w03 = wr0.w;
    const float w10 = wr1.x, w11 = wr1.y, w12 = wr1.z, w13 = wr1.w;
    const float w20 = wr2.x, w21 = wr2.y, w22 = wr2.z, w23 = wr2.w;
    const float w30 = wr3.x, w31 = wr3.y, w32 = wr3.z, w33 = wr3.w;

    float* sb = sbuf + 4 * t;

    // Even output row 2r: input rows (r-1 -> w3*), (r -> w1*)
    // Odd  output row 2r+1: input rows (r -> w2*), (r+1 -> w0*)
    // With r = 4g + k (k=0..3): r-1 -> j=k, r -> j=k+1, r+1 -> j=k+2.
#define OUT_ROW(rowidx, ja, a0_, a1_, a2_, a3_, jb, c0_, c1_, c2_, c3_)        \
    {                                                                          \
        float4 o;                                                              \
        o.x = a3_ * L[ja]  + a1_ * cx[ja] + c3_ * L[jb]  + c1_ * cx[jb] + b0;  \
        o.y = a2_ * cx[ja] + a0_ * cy[ja] + c2_ * cx[jb] + c0_ * cy[jb] + b0;  \
        o.z = a3_ * cx[ja] + a1_ * cy[ja] + c3_ * cx[jb] + c1_ * cy[jb] + b0;  \
        o.w = a2_ * cy[ja] + a0_ * R[ja]  + c2_ * cy[jb] + c0_ * R[jb]  + b0;  \
        *reinterpret_cast<float4*>(sb + (rowidx) * OW) = o;                    \
    }

    OUT_ROW(0, 0, w30, w31, w32, w33, 1, w10, w11, w12, w13);
    OUT_ROW(1, 1, w20, w21, w22, w23, 2, w00, w01, w02, w03);
    OUT_ROW(2, 1, w30, w31, w32, w33, 2, w10, w11, w12, w13);
    OUT_ROW(3, 2, w20, w21, w22, w23, 3, w00, w01, w02, w03);
    OUT_ROW(4, 2, w30, w31, w32, w33, 3, w10, w11, w12, w13);
    OUT_ROW(5, 3, w20, w21, w22, w23, 4, w00, w01, w02, w03);
    OUT_ROW(6, 3, w30, w31, w32, w33, 4, w10, w11, w12, w13);
    OUT_ROW(7, 4, w20, w21, w22, w23, 5, w00, w01, w02, w03);
#undef OUT_ROW

    // Make smem writes visible to the async (bulk-copy) proxy, then push the
    // whole contiguous 16KB tile with one bulk store.
    asm volatile("fence.proxy.async.shared::cta;" ::: "memory");
    __syncthreads();

    if (t == 0) {
        float* gdst = out + (size_t)bs * (OH * OW) + (size_t)8 * g * OW;
        uint32_t saddr;
        asm("{ .reg .u64 a; cvta.to.shared.u64 a, %1; cvt.u32.u64 %0, a; }"
            : "=r"(saddr) : "l"(sbuf));
        asm volatile(
            "cp.async.bulk.global.shared::cta.bulk_group [%0], [%1], %2;"
            :: "l"(gdst), "r"(saddr), "r"(8 * OW * 4) : "memory");
        asm volatile("cp.async.bulk.commit_group;" ::: "memory");
        // Wait only until the bulk engine has READ the smem (safe to free).
        asm volatile("cp.async.bulk.wait_group.read 0;" ::: "memory");
    }
}

extern "C" void kernel_launch(void* const* d_in, const int* in_sizes, int n_in,
                              void* d_out, int out_size) {
    const float* x = (const float*)d_in[0];
    const float* w = (const float*)d_in[1];
    const float* b = (const float*)d_in[2];
    float* out = (float*)d_out;

    const int B = in_sizes[0] / (NSLICE * H * W);   // = 8
    dim3 grid(OH / 8, B * NSLICE);                   // 64 x 192
    convT_kernel<<<grid, 128>>>(x, w, b, out);
}